// round 2
// baseline (speedup 1.0000x reference)
#include <cuda_runtime.h>
#include <cstdint>

#define BATCH  64
#define SEQ    512
#define INDIM  512
#define HID    1024
#define OUTDIM 512

// ---------------- device scratch (static allocation is the sanctioned path) ---
__device__ float    g_xp[(size_t)BATCH * SEQ * HID];   // 128 MB x-projection
__device__ float    g_h[2 * BATCH * HID];              // ping-pong hidden state
__device__ unsigned g_bar;                             // global barrier counter

// ---------------- packed f32x2 helpers --------------------------------------
__device__ __forceinline__ double pack2(float lo, float hi) {
    double d;
    asm("mov.b64 %0, {%1, %2};" : "=d"(d) : "f"(lo), "f"(hi));
    return d;
}
__device__ __forceinline__ void unpack2(double d, float &lo, float &hi) {
    asm("mov.b64 {%0, %1}, %2;" : "=f"(lo), "=f"(hi) : "d"(d));
}
__device__ __forceinline__ void ffma2(double &acc, double a, double b) {
    asm("fma.rn.f32x2 %0, %1, %2, %0;" : "+d"(acc) : "d"(a), "d"(b));
}

// ---------------- init: zero hidden buffers + barrier ------------------------
__global__ void k_init() {
    int i = blockIdx.x * blockDim.x + threadIdx.x;
    if (i == 0) g_bar = 0u;
    if (i < 2 * BATCH * HID) g_h[i] = 0.0f;
}

// ---------------- x_proj GEMM: C[32768,1024] = X @ W_ih^T + (b_ih+b_hh) ------
// BM=128, BN=128, BK=16, 256 threads, 8m x 8n per thread, FFMA2 over m-pairs.
#define XP_BK 16

__global__ __launch_bounds__(256) void k_xproj(
    const float* __restrict__ X, const float* __restrict__ Wih,
    const float* __restrict__ bih, const float* __restrict__ bhh)
{
    __shared__ float As[XP_BK][132];   // transposed: [k][m], pad 132
    __shared__ float Bs[XP_BK][132];   // transposed: [k][n], pad 132

    const int tid = threadIdx.x;
    const int tx  = tid & 15;          // n direction
    const int ty  = tid >> 4;          // m direction
    const int m0  = blockIdx.x * 128;
    const int n0  = blockIdx.y * 128;
    const int tm0 = ty * 8;
    const int tn0 = tx * 8;

    double acc[4][8];                  // [m-pair][n]
#pragma unroll
    for (int i = 0; i < 4; i++)
#pragma unroll
        for (int j = 0; j < 8; j++) acc[i][j] = 0.0;

    const float* Ag = X   + (size_t)m0 * INDIM;
    const float* Bg = Wih + (size_t)n0 * INDIM;

    float4 pa[2], pb[2];
#pragma unroll
    for (int r = 0; r < 2; r++) {
        int p = tid + 256 * r;             // f4 index: row = p>>2, k4 = p&3
        pa[r] = *(const float4*)(Ag + (size_t)(p >> 2) * INDIM + (p & 3) * 4);
        pb[r] = *(const float4*)(Bg + (size_t)(p >> 2) * INDIM + (p & 3) * 4);
    }

    for (int kt = 0; kt < INDIM / XP_BK; kt++) {
        // store prefetched tile (transposed)
#pragma unroll
        for (int r = 0; r < 2; r++) {
            int p = tid + 256 * r;
            int row = p >> 2, kk = (p & 3) * 4;
            As[kk + 0][row] = pa[r].x; As[kk + 1][row] = pa[r].y;
            As[kk + 2][row] = pa[r].z; As[kk + 3][row] = pa[r].w;
            Bs[kk + 0][row] = pb[r].x; Bs[kk + 1][row] = pb[r].y;
            Bs[kk + 2][row] = pb[r].z; Bs[kk + 3][row] = pb[r].w;
        }
        __syncthreads();

        if (kt + 1 < INDIM / XP_BK) {
            int k1 = (kt + 1) * XP_BK;
#pragma unroll
            for (int r = 0; r < 2; r++) {
                int p = tid + 256 * r;
                pa[r] = *(const float4*)(Ag + (size_t)(p >> 2) * INDIM + (p & 3) * 4 + k1);
                pb[r] = *(const float4*)(Bg + (size_t)(p >> 2) * INDIM + (p & 3) * 4 + k1);
            }
        }

#pragma unroll
        for (int k = 0; k < XP_BK; k++) {
            double2 aq0 = *(const double2*)&As[k][tm0];
            double2 aq1 = *(const double2*)&As[k][tm0 + 4];
            double am[4] = {aq0.x, aq0.y, aq1.x, aq1.y};
            float4 bq0 = *(const float4*)&Bs[k][tn0];
            float4 bq1 = *(const float4*)&Bs[k][tn0 + 4];
            double bd[8];
            bd[0] = pack2(bq0.x, bq0.x); bd[1] = pack2(bq0.y, bq0.y);
            bd[2] = pack2(bq0.z, bq0.z); bd[3] = pack2(bq0.w, bq0.w);
            bd[4] = pack2(bq1.x, bq1.x); bd[5] = pack2(bq1.y, bq1.y);
            bd[6] = pack2(bq1.z, bq1.z); bd[7] = pack2(bq1.w, bq1.w);
#pragma unroll
            for (int i = 0; i < 4; i++)
#pragma unroll
                for (int j = 0; j < 8; j++) ffma2(acc[i][j], am[i], bd[j]);
        }
        __syncthreads();
    }

    // epilogue: bias + store
    float bias[8];
#pragma unroll
    for (int j = 0; j < 8; j++)
        bias[j] = __ldg(&bih[n0 + tn0 + j]) + __ldg(&bhh[n0 + tn0 + j]);

    float* C = g_xp + (size_t)(m0 + tm0) * HID + n0 + tn0;
#pragma unroll
    for (int i = 0; i < 4; i++) {
        float lo[8], hi[8];
#pragma unroll
        for (int j = 0; j < 8; j++) {
            unpack2(acc[i][j], lo[j], hi[j]);
            lo[j] += bias[j]; hi[j] += bias[j];
        }
        float* r0 = C + (size_t)(2 * i) * HID;
        float* r1 = r0 + HID;
        ((float4*)r0)[0] = make_float4(lo[0], lo[1], lo[2], lo[3]);
        ((float4*)r0)[1] = make_float4(lo[4], lo[5], lo[6], lo[7]);
        ((float4*)r1)[0] = make_float4(hi[0], hi[1], hi[2], hi[3]);
        ((float4*)r1)[1] = make_float4(hi[4], hi[5], hi[6], hi[7]);
    }
}

// ---------------- recurrence: persistent kernel ------------------------------
#define R_CTAS    128
#define R_THREADS 256
// smem floats: W slice 32*1024, h double-buffer 2*16*256, reduction 32*513
#define R_SMEM_FLOATS (32 * 1024 + 2 * 16 * 256 + 32 * 513)
#define R_SMEM_BYTES  (R_SMEM_FLOATS * 4)

__device__ __forceinline__ void issue_chunk(float* dst, const float* gsrc, int tid) {
    // copy 16 rows x 256 floats; global row stride HID, smem row stride 256
#pragma unroll
    for (int r = 0; r < 4; r++) {
        int q   = tid + R_THREADS * r;     // f4 index, 1024 total
        int row = q >> 6, c4 = q & 63;
        unsigned saddr = (unsigned)__cvta_generic_to_shared(dst + row * 256 + c4 * 4);
        const float* g = gsrc + (size_t)row * HID + c4 * 4;
        asm volatile("cp.async.cg.shared.global [%0], [%1], 16;" :: "r"(saddr), "l"(g));
    }
}

__global__ __launch_bounds__(R_THREADS, 1) void k_recur(const float* __restrict__ Whh)
{
    extern __shared__ float sm[];
    float* Ws   = sm;                              // [32][1024]
    float* hbuf = sm + 32 * 1024;                  // [2][16][256]
    float* red  = sm + 32 * 1024 + 2 * 16 * 256;   // [32][513]

    const int tid = threadIdx.x;
    const int s   = tid & 31;          // k-split lane
    const int g   = tid >> 5;          // warp 0..7
    const int bg  = g & 1;             // batch sub-group (8 rows)
    const int jg  = g >> 1;            // j sub-group (8 rows)
    const int cta_j0 = (blockIdx.x & 31) * 32;
    const int cta_b0 = (blockIdx.x >> 5) * 16;

    // load W_hh slice (32 rows x 1024) into smem, resident for all 512 steps
    {
        const float* Wg = Whh + (size_t)cta_j0 * HID;
#pragma unroll
        for (int r = 0; r < 32; r++) {
            int q  = tid + R_THREADS * r;          // f4 index, 8192 total
            int jl = q >> 8, k4 = q & 255;
            *(float4*)(Ws + jl * HID + k4 * 4) =
                *(const float4*)(Wg + (size_t)jl * HID + k4 * 4);
        }
    }
    __syncthreads();

    const int o0  = tid * 2, o1 = o0 + 1;
    const int bl0 = o0 >> 5, jl0 = o0 & 31;
    const int bl1 = o1 >> 5, jl1 = o1 & 31;

    unsigned bar_target = 0;

    for (int t = 0; t < SEQ; t++) {
        const float* hc = g_h + (t & 1) * (BATCH * HID);
        float*       hn = g_h + ((t + 1) & 1) * (BATCH * HID);

        // prefetch x-projection values for this thread's two outputs
        float xp0 = __ldg(&g_xp[((size_t)(cta_b0 + bl0) * SEQ + t) * HID + cta_j0 + jl0]);
        float xp1 = __ldg(&g_xp[((size_t)(cta_b0 + bl1) * SEQ + t) * HID + cta_j0 + jl1]);

        double acc[8][8];
#pragma unroll
        for (int i = 0; i < 8; i++)
#pragma unroll
            for (int j = 0; j < 8; j++) acc[i][j] = 0.0;

        // pipelined h staging: 4 chunks of 256 k, double-buffered cp.async
        issue_chunk(hbuf, hc + (size_t)cta_b0 * HID, tid);
        asm volatile("cp.async.commit_group;");

#pragma unroll
        for (int c = 0; c < 4; c++) {
            if (c < 3) {
                issue_chunk(hbuf + ((c + 1) & 1) * (16 * 256),
                            hc + (size_t)cta_b0 * HID + (c + 1) * 256, tid);
                asm volatile("cp.async.commit_group;");
                asm volatile("cp.async.wait_group 1;");
            } else {
                asm volatile("cp.async.wait_group 0;");
            }
            __syncthreads();

            const float* hb = hbuf + (c & 1) * (16 * 256);
#pragma unroll
            for (int r = 0; r < 2; r++) {
                const int koff = r * 128 + s * 4;
                double2 h2[8], w2[8];
#pragma unroll
                for (int i = 0; i < 8; i++)
                    h2[i] = *(const double2*)(hb + (bg * 8 + i) * 256 + koff);
#pragma unroll
                for (int j = 0; j < 8; j++)
                    w2[j] = *(const double2*)(Ws + (jg * 8 + j) * HID + c * 256 + koff);
#pragma unroll
                for (int i = 0; i < 8; i++)
#pragma unroll
                    for (int j = 0; j < 8; j++) {
                        ffma2(acc[i][j], h2[i].x, w2[j].x);
                        ffma2(acc[i][j], h2[i].y, w2[j].y);
                    }
            }
            __syncthreads();
        }

        // write split-k partials (pad 513 -> conflict-free across s)
#pragma unroll
        for (int i = 0; i < 8; i++)
#pragma unroll
            for (int j = 0; j < 8; j++) {
                float lo, hi; unpack2(acc[i][j], lo, hi);
                int o = (bg * 8 + i) * 32 + (jg * 8 + j);
                red[s * 513 + o] = lo + hi;
            }
        __syncthreads();

        // reduce 32 partials for two outputs, add xp, tanh, store
        float v0 = 0.0f, v1 = 0.0f;
#pragma unroll
        for (int ss = 0; ss < 32; ss++) {
            v0 += red[ss * 513 + o0];
            v1 += red[ss * 513 + o1];
        }
        v0 = tanhf(v0 + xp0);
        v1 = tanhf(v1 + xp1);
        *(float2*)(hn + (size_t)(cta_b0 + bl0) * HID + cta_j0 + jl0) = make_float2(v0, v1);

        // global barrier (all 128 CTAs resident: 1 CTA/SM via 229KB smem)
        __threadfence();
        __syncthreads();
        bar_target += R_CTAS;
        if (tid == 0) {
            atomicAdd(&g_bar, 1u);
            volatile unsigned* p = &g_bar;
            while (*p < bar_target) { }
        }
        __syncthreads();
    }
}

// ---------------- output projection: out[b][o] = h_final[b] . W_ho[o] + b_ho -
__global__ void k_out(const float* __restrict__ Who, const float* __restrict__ bho,
                      float* __restrict__ out)
{
    int gid = blockIdx.x * blockDim.x + threadIdx.x;  // 32768
    int o = gid >> 6;          // same o across a warp -> W broadcast
    int b = gid & 63;
    const float4* hr = (const float4*)(g_h + (size_t)b * HID);  // final h in buf 0
    const float4* wr = (const float4*)(Who + (size_t)o * HID);
    float s0 = 0.f, s1 = 0.f, s2 = 0.f, s3 = 0.f;
#pragma unroll 4
    for (int i = 0; i < HID / 4; i += 2) {
        float4 h0 = hr[i],     w0 = wr[i];
        float4 h1 = hr[i + 1], w1 = wr[i + 1];
        s0 += h0.x * w0.x + h1.x * w1.x;
        s1 += h0.y * w0.y + h1.y * w1.y;
        s2 += h0.z * w0.z + h1.z * w1.z;
        s3 += h0.w * w0.w + h1.w * w1.w;
    }
    out[b * OUTDIM + o] = s0 + s1 + s2 + s3 + __ldg(&bho[o]);
}

// ---------------- launch ------------------------------------------------------
extern "C" void kernel_launch(void* const* d_in, const int* in_sizes, int n_in,
                              void* d_out, int out_size)
{
    (void)in_sizes; (void)n_in; (void)out_size;
    const float* X   = (const float*)d_in[0];
    const float* Wih = (const float*)d_in[1];
    const float* bih = (const float*)d_in[2];
    const float* Whh = (const float*)d_in[3];
    const float* bhh = (const float*)d_in[4];
    const float* Who = (const float*)d_in[5];
    const float* bho = (const float*)d_in[6];
    float* out = (float*)d_out;

    cudaFuncSetAttribute(k_recur, cudaFuncAttributeMaxDynamicSharedMemorySize,
                         R_SMEM_BYTES);

    k_init<<<512, 256>>>();
    dim3 xg(256, 8);
    k_xproj<<<xg, 256>>>(X, Wih, bih, bhh);
    k_recur<<<R_CTAS, R_THREADS, R_SMEM_BYTES>>>(Whh);
    k_out<<<32768 / 256, 256>>>(Who, bho, out);
}

// round 3
// speedup vs baseline: 1.3745x; 1.3745x over previous
#include <cuda_runtime.h>
#include <cuda_bf16.h>
#include <cstdint>

#define BATCH  64
#define SEQ    512
#define INDIM  512
#define HID    1024
#define OUTDIM 512

// ---------------- device scratch ---------------------------------------------
__device__ float          g_xp[(size_t)BATCH * SEQ * HID];   // 128 MB x-projection
__device__ __nv_bfloat16  g_hhi[2 * BATCH * HID];            // hidden state hi (ping-pong)
__device__ __nv_bfloat16  g_hlo[2 * BATCH * HID];            // hidden state lo
__device__ __nv_bfloat16  g_whi[(size_t)HID * HID];          // W_hh hi
__device__ __nv_bfloat16  g_wlo[(size_t)HID * HID];          // W_hh lo
__device__ unsigned       g_bar;

// ---------------- packed f32x2 helpers (xproj) -------------------------------
__device__ __forceinline__ double pack2(float lo, float hi) {
    double d;
    asm("mov.b64 %0, {%1, %2};" : "=d"(d) : "f"(lo), "f"(hi));
    return d;
}
__device__ __forceinline__ void unpack2(double d, float &lo, float &hi) {
    asm("mov.b64 {%0, %1}, %2;" : "=f"(lo), "=f"(hi) : "d"(d));
}
__device__ __forceinline__ void ffma2(double &acc, double a, double b) {
    asm("fma.rn.f32x2 %0, %1, %2, %0;" : "+d"(acc) : "d"(a), "d"(b));
}

// ---------------- mma / ldmatrix helpers -------------------------------------
__device__ __forceinline__ void ldsm4(uint32_t &r0, uint32_t &r1, uint32_t &r2,
                                      uint32_t &r3, uint32_t addr) {
    asm volatile("ldmatrix.sync.aligned.m8n8.x4.shared.b16 {%0,%1,%2,%3}, [%4];"
                 : "=r"(r0), "=r"(r1), "=r"(r2), "=r"(r3) : "r"(addr));
}
__device__ __forceinline__ void mma16816(float* d, uint32_t a0, uint32_t a1,
                                         uint32_t a2, uint32_t a3,
                                         uint32_t b0, uint32_t b1) {
    asm volatile(
        "mma.sync.aligned.m16n8k16.row.col.f32.bf16.bf16.f32 "
        "{%0,%1,%2,%3},{%4,%5,%6,%7},{%8,%9},{%0,%1,%2,%3};"
        : "+f"(d[0]), "+f"(d[1]), "+f"(d[2]), "+f"(d[3])
        : "r"(a0), "r"(a1), "r"(a2), "r"(a3), "r"(b0), "r"(b1));
}

// ---------------- init: zero hidden buffers + barrier ------------------------
__global__ void k_init() {
    int i = blockIdx.x * blockDim.x + threadIdx.x;    // 131072 threads
    if (i == 0) g_bar = 0u;
    // each thread zeroes one u32 (2 bf16); 65536 u32 per array
    if (i < 65536)       ((uint32_t*)g_hhi)[i] = 0u;
    else                 ((uint32_t*)g_hlo)[i - 65536] = 0u;
}

// ---------------- W_hh split into bf16 hi/lo ---------------------------------
__global__ void k_wprep(const float* __restrict__ Whh) {
    int i = blockIdx.x * blockDim.x + threadIdx.x;    // 1M threads
    float w = Whh[i];
    __nv_bfloat16 hi = __float2bfloat16(w);
    __nv_bfloat16 lo = __float2bfloat16(w - __bfloat162float(hi));
    g_whi[i] = hi;
    g_wlo[i] = lo;
}

// ---------------- x_proj GEMM: C[32768,1024] = X @ W_ih^T + (b_ih+b_hh) ------
#define XP_BK 16

__global__ __launch_bounds__(256) void k_xproj(
    const float* __restrict__ X, const float* __restrict__ Wih,
    const float* __restrict__ bih, const float* __restrict__ bhh)
{
    __shared__ float As[XP_BK][132];
    __shared__ float Bs[XP_BK][132];

    const int tid = threadIdx.x;
    const int tx  = tid & 15;
    const int ty  = tid >> 4;
    const int m0  = blockIdx.x * 128;
    const int n0  = blockIdx.y * 128;
    const int tm0 = ty * 8;
    const int tn0 = tx * 8;

    double acc[4][8];
#pragma unroll
    for (int i = 0; i < 4; i++)
#pragma unroll
        for (int j = 0; j < 8; j++) acc[i][j] = 0.0;

    const float* Ag = X   + (size_t)m0 * INDIM;
    const float* Bg = Wih + (size_t)n0 * INDIM;

    float4 pa[2], pb[2];
#pragma unroll
    for (int r = 0; r < 2; r++) {
        int p = tid + 256 * r;
        pa[r] = *(const float4*)(Ag + (size_t)(p >> 2) * INDIM + (p & 3) * 4);
        pb[r] = *(const float4*)(Bg + (size_t)(p >> 2) * INDIM + (p & 3) * 4);
    }

    for (int kt = 0; kt < INDIM / XP_BK; kt++) {
#pragma unroll
        for (int r = 0; r < 2; r++) {
            int p = tid + 256 * r;
            int row = p >> 2, kk = (p & 3) * 4;
            As[kk + 0][row] = pa[r].x; As[kk + 1][row] = pa[r].y;
            As[kk + 2][row] = pa[r].z; As[kk + 3][row] = pa[r].w;
            Bs[kk + 0][row] = pb[r].x; Bs[kk + 1][row] = pb[r].y;
            Bs[kk + 2][row] = pb[r].z; Bs[kk + 3][row] = pb[r].w;
        }
        __syncthreads();

        if (kt + 1 < INDIM / XP_BK) {
            int k1 = (kt + 1) * XP_BK;
#pragma unroll
            for (int r = 0; r < 2; r++) {
                int p = tid + 256 * r;
                pa[r] = *(const float4*)(Ag + (size_t)(p >> 2) * INDIM + (p & 3) * 4 + k1);
                pb[r] = *(const float4*)(Bg + (size_t)(p >> 2) * INDIM + (p & 3) * 4 + k1);
            }
        }

#pragma unroll
        for (int k = 0; k < XP_BK; k++) {
            double2 aq0 = *(const double2*)&As[k][tm0];
            double2 aq1 = *(const double2*)&As[k][tm0 + 4];
            double am[4] = {aq0.x, aq0.y, aq1.x, aq1.y};
            float4 bq0 = *(const float4*)&Bs[k][tn0];
            float4 bq1 = *(const float4*)&Bs[k][tn0 + 4];
            double bd[8];
            bd[0] = pack2(bq0.x, bq0.x); bd[1] = pack2(bq0.y, bq0.y);
            bd[2] = pack2(bq0.z, bq0.z); bd[3] = pack2(bq0.w, bq0.w);
            bd[4] = pack2(bq1.x, bq1.x); bd[5] = pack2(bq1.y, bq1.y);
            bd[6] = pack2(bq1.z, bq1.z); bd[7] = pack2(bq1.w, bq1.w);
#pragma unroll
            for (int i = 0; i < 4; i++)
#pragma unroll
                for (int j = 0; j < 8; j++) ffma2(acc[i][j], am[i], bd[j]);
        }
        __syncthreads();
    }

    float bias[8];
#pragma unroll
    for (int j = 0; j < 8; j++)
        bias[j] = __ldg(&bih[n0 + tn0 + j]) + __ldg(&bhh[n0 + tn0 + j]);

    float* C = g_xp + (size_t)(m0 + tm0) * HID + n0 + tn0;
#pragma unroll
    for (int i = 0; i < 4; i++) {
        float lo[8], hi[8];
#pragma unroll
        for (int j = 0; j < 8; j++) {
            unpack2(acc[i][j], lo[j], hi[j]);
            lo[j] += bias[j]; hi[j] += bias[j];
        }
        float* r0 = C + (size_t)(2 * i) * HID;
        float* r1 = r0 + HID;
        ((float4*)r0)[0] = make_float4(lo[0], lo[1], lo[2], lo[3]);
        ((float4*)r0)[1] = make_float4(lo[4], lo[5], lo[6], lo[7]);
        ((float4*)r1)[0] = make_float4(hi[0], hi[1], hi[2], hi[3]);
        ((float4*)r1)[1] = make_float4(hi[4], hi[5], hi[6], hi[7]);
    }
}

// ---------------- recurrence: persistent tensor-core kernel ------------------
// 128 CTAs x 256 threads. CTA tile: 16 batch x 32 j, K=1024 split 2 chunks x
// (8 warps x 64 k). W_hh slice resident in smem as bf16 hi/lo (padded rows).
#define R_CTAS    128
#define R_THREADS 256

// smem byte layout (all row strides odd multiples of 16B -> ldmatrix conflict-free)
#define SM_WHI   0                       // [32][1032] bf16  (row 2064 B)
#define SM_WLO   66048
#define SM_HBUF  132096                  // 2 chunk bufs x 2 comps x [16][520] bf16
#define HB_CHUNK 33280
#define HB_COMP  16640
#define HB_ROW   1040
#define SM_RED   198656                  // [8][528] f32
#define RED_ROW  528
#define SM_BYTES 215552

__device__ __forceinline__ void stage_chunk(uint32_t dst_base,
                                            const __nv_bfloat16* ghi,
                                            const __nv_bfloat16* glo, int tid) {
    // 2 comps x 16 rows x 64 x 16B granules = 2048; 8 per thread
#pragma unroll
    for (int r = 0; r < 8; r++) {
        int q    = tid + R_THREADS * r;
        int comp = q >> 10, rr = (q >> 6) & 15, g = q & 63;
        const __nv_bfloat16* src = (comp ? glo : ghi) + rr * HID + g * 8;
        uint32_t dst = dst_base + comp * HB_COMP + rr * HB_ROW + g * 16;
        asm volatile("cp.async.cg.shared.global [%0], [%1], 16;"
                     :: "r"(dst), "l"(src));
    }
}

__global__ __launch_bounds__(R_THREADS, 1) void k_recur()
{
    extern __shared__ char smc[];
    const uint32_t smb = (uint32_t)__cvta_generic_to_shared(smc);
    float* redf = (float*)(smc + SM_RED);

    const int tid  = threadIdx.x;
    const int lane = tid & 31;
    const int w    = tid >> 5;            // warp 0..7 (k-split)
    const int cta_j0 = (blockIdx.x & 31) * 32;
    const int cta_b0 = (blockIdx.x >> 5) * 16;

    // ---- load W slice (32 j x 1024 k, hi+lo) into padded smem ----
#pragma unroll 8
    for (int it = 0; it < 32; it++) {
        int q = tid + R_THREADS * it;            // 0..8191 uint4
        int comp = q >> 12, row = (q >> 7) & 31, g = q & 127;
        const __nv_bfloat16* src =
            (comp ? g_wlo : g_whi) + (size_t)(cta_j0 + row) * HID + g * 8;
        *(uint4*)(smc + (comp ? SM_WLO : SM_WHI) + row * 2064 + g * 16) =
            *(const uint4*)src;
    }
    __syncthreads();

    // ---- per-lane ldmatrix base addresses ----
    // A (h): x4 covers m16 x k16: lanes 0-15 rows, k+0; 16-31 rows, k+8
    uint32_t a_base[2];
#pragma unroll
    for (int comp = 0; comp < 2; comp++)
        a_base[comp] = smb + SM_HBUF + comp * HB_COMP
                     + (lane & 15) * HB_ROW + (lane >> 4) * 16;
    // B (W): x4 covers n16 x k16 (two n8 tiles)
    uint32_t b_base[2][2];
#pragma unroll
    for (int comp = 0; comp < 2; comp++)
#pragma unroll
        for (int half = 0; half < 2; half++)
            b_base[comp][half] = smb + (comp ? SM_WLO : SM_WHI)
                + (half * 16 + (lane >> 4) * 8 + (lane & 7)) * 2064
                + ((lane >> 3) & 1) * 16;

    const int koffw = w * 128;                    // bytes: w*64 elems

    // output mapping for reduction consumer
    const int o0 = tid * 2;
    const int bl = o0 >> 5, jl = o0 & 31;

    unsigned bar_target = 0;

    for (int t = 0; t < SEQ; t++) {
        const __nv_bfloat16* hch = g_hhi + (t & 1) * (BATCH * HID) + cta_b0 * HID;
        const __nv_bfloat16* hcl = g_hlo + (t & 1) * (BATCH * HID) + cta_b0 * HID;
        __nv_bfloat16* hnh = g_hhi + ((t + 1) & 1) * (BATCH * HID);
        __nv_bfloat16* hnl = g_hlo + ((t + 1) & 1) * (BATCH * HID);

        // prefetch x-projection pair (j even, float2-aligned)
        float2 xp = __ldg((const float2*)
            (g_xp + ((size_t)(cta_b0 + bl) * SEQ + t) * HID + cta_j0 + jl));

        float D1[4][4], D2[4][4];
#pragma unroll
        for (int i = 0; i < 4; i++)
#pragma unroll
            for (int j = 0; j < 4; j++) { D1[i][j] = 0.f; D2[i][j] = 0.f; }

        stage_chunk(smb + SM_HBUF, hch, hcl, tid);
        asm volatile("cp.async.commit_group;");

#pragma unroll
        for (int c = 0; c < 2; c++) {
            if (c == 0) {
                stage_chunk(smb + SM_HBUF + HB_CHUNK, hch + 512, hcl + 512, tid);
                asm volatile("cp.async.commit_group;");
                asm volatile("cp.async.wait_group 1;");
            } else {
                asm volatile("cp.async.wait_group 0;");
            }
            __syncthreads();

            const uint32_t cb = c * HB_CHUNK;
            const uint32_t cw = c * 1024;          // W k-offset bytes
#pragma unroll
            for (int ks = 0; ks < 4; ks++) {
                const uint32_t ka = koffw + ks * 32;
                uint32_t ah[4], al[4], bh[2][4], bl2[2][4];
                ldsm4(ah[0], ah[1], ah[2], ah[3], a_base[0] + cb + ka);
                ldsm4(al[0], al[1], al[2], al[3], a_base[1] + cb + ka);
                ldsm4(bh[0][0], bh[0][1], bh[0][2], bh[0][3], b_base[0][0] + cw + ka);
                ldsm4(bh[1][0], bh[1][1], bh[1][2], bh[1][3], b_base[0][1] + cw + ka);
                ldsm4(bl2[0][0], bl2[0][1], bl2[0][2], bl2[0][3], b_base[1][0] + cw + ka);
                ldsm4(bl2[1][0], bl2[1][1], bl2[1][2], bl2[1][3], b_base[1][1] + cw + ka);
#pragma unroll
                for (int tt = 0; tt < 4; tt++) {
                    int h2 = tt >> 1, p = (tt & 1) * 2;
                    mma16816(D1[tt], ah[0], ah[1], ah[2], ah[3],
                             bh[h2][p], bh[h2][p + 1]);
                }
#pragma unroll
                for (int tt = 0; tt < 4; tt++) {
                    int h2 = tt >> 1, p = (tt & 1) * 2;
                    mma16816(D2[tt], al[0], al[1], al[2], al[3],
                             bh[h2][p], bh[h2][p + 1]);
                }
#pragma unroll
                for (int tt = 0; tt < 4; tt++) {
                    int h2 = tt >> 1, p = (tt & 1) * 2;
                    mma16816(D2[tt], ah[0], ah[1], ah[2], ah[3],
                             bl2[h2][p], bl2[h2][p + 1]);
                }
            }
            __syncthreads();
        }

        // ---- cross-warp k reduction via smem ----
#pragma unroll
        for (int tt = 0; tt < 4; tt++)
#pragma unroll
            for (int r = 0; r < 4; r++) {
                int b = (lane >> 2) + ((r >= 2) ? 8 : 0);
                int j = tt * 8 + 2 * (lane & 3) + (r & 1);
                redf[w * RED_ROW + b * 33 + j] = D1[tt][r] + D2[tt][r];
            }
        __syncthreads();

        float v0 = 0.f, v1 = 0.f;
#pragma unroll
        for (int ww = 0; ww < 8; ww++) {
            v0 += redf[ww * RED_ROW + bl * 33 + jl];
            v1 += redf[ww * RED_ROW + bl * 33 + jl + 1];
        }
        v0 = tanhf(v0 + xp.x);
        v1 = tanhf(v1 + xp.y);

        __nv_bfloat16 h0 = __float2bfloat16(v0);
        __nv_bfloat16 h1 = __float2bfloat16(v1);
        __nv_bfloat16 l0 = __float2bfloat16(v0 - __bfloat162float(h0));
        __nv_bfloat16 l1 = __float2bfloat16(v1 - __bfloat162float(h1));
        size_t oidx = (size_t)(cta_b0 + bl) * HID + cta_j0 + jl;
        __nv_bfloat162 ph; ph.x = h0; ph.y = h1;
        __nv_bfloat162 pl; pl.x = l0; pl.y = l1;
        *(__nv_bfloat162*)(hnh + oidx) = ph;
        *(__nv_bfloat162*)(hnl + oidx) = pl;

        // ---- global barrier (all 128 CTAs resident, 1 CTA/SM) ----
        __threadfence();
        __syncthreads();
        bar_target += R_CTAS;
        if (tid == 0) {
            atomicAdd(&g_bar, 1u);
            volatile unsigned* p = &g_bar;
            while (*p < bar_target) { }
        }
        __syncthreads();
    }
}

// ---------------- output projection ------------------------------------------
// warp handles 2 outputs x 8 batch rows; W rows cached in registers.
__global__ __launch_bounds__(256) void k_out(
    const float* __restrict__ Who, const float* __restrict__ bho,
    float* __restrict__ out)
{
    const int lane = threadIdx.x & 31;
    const int gw   = blockIdx.x * 8 + (threadIdx.x >> 5);   // 0..2047
    const int o0   = (gw >> 3) * 2;
    const int b0   = (gw & 7) * 8;

    const float4* W0 = (const float4*)(Who + (size_t)o0 * HID);
    const float4* W1 = (const float4*)(Who + (size_t)(o0 + 1) * HID);
    float4 wr0[8], wr1[8];
#pragma unroll
    for (int i = 0; i < 8; i++) {
        wr0[i] = W0[i * 32 + lane];
        wr1[i] = W1[i * 32 + lane];
    }
    float bias0 = __ldg(&bho[o0]), bias1 = __ldg(&bho[o0 + 1]);

#pragma unroll
    for (int b = 0; b < 8; b++) {
        const __nv_bfloat16* hh = g_hhi + (size_t)(b0 + b) * HID;  // final h in buf 0
        const __nv_bfloat16* hl = g_hlo + (size_t)(b0 + b) * HID;
        float a0 = 0.f, a1 = 0.f;
#pragma unroll
        for (int i = 0; i < 8; i++) {
            int k0 = lane * 4 + i * 128;
            __nv_bfloat162 ph0 = *(const __nv_bfloat162*)(hh + k0);
            __nv_bfloat162 ph1 = *(const __nv_bfloat162*)(hh + k0 + 2);
            __nv_bfloat162 pl0 = *(const __nv_bfloat162*)(hl + k0);
            __nv_bfloat162 pl1 = *(const __nv_bfloat162*)(hl + k0 + 2);
            float2 f0 = __bfloat1622float2(ph0), g0 = __bfloat1622float2(pl0);
            float2 f1 = __bfloat1622float2(ph1), g1 = __bfloat1622float2(pl1);
            float hx = f0.x + g0.x, hy = f0.y + g0.y;
            float hz = f1.x + g1.x, hw = f1.y + g1.y;
            a0 += hx * wr0[i].x + hy * wr0[i].y + hz * wr0[i].z + hw * wr0[i].w;
            a1 += hx * wr1[i].x + hy * wr1[i].y + hz * wr1[i].z + hw * wr1[i].w;
        }
#pragma unroll
        for (int off = 16; off; off >>= 1) {
            a0 += __shfl_xor_sync(0xffffffffu, a0, off);
            a1 += __shfl_xor_sync(0xffffffffu, a1, off);
        }
        if (lane == 0) {
            out[(size_t)(b0 + b) * OUTDIM + o0]     = a0 + bias0;
            out[(size_t)(b0 + b) * OUTDIM + o0 + 1] = a1 + bias1;
        }
    }
}

// ---------------- launch ------------------------------------------------------
extern "C" void kernel_launch(void* const* d_in, const int* in_sizes, int n_in,
                              void* d_out, int out_size)
{
    (void)in_sizes; (void)n_in; (void)out_size;
    const float* X   = (const float*)d_in[0];
    const float* Wih = (const float*)d_in[1];
    const float* bih = (const float*)d_in[2];
    const float* Whh = (const float*)d_in[3];
    const float* bhh = (const float*)d_in[4];
    const float* Who = (const float*)d_in[5];
    const float* bho = (const float*)d_in[6];
    float* out = (float*)d_out;

    cudaFuncSetAttribute(k_recur, cudaFuncAttributeMaxDynamicSharedMemorySize,
                         SM_BYTES);

    k_init<<<512, 256>>>();
    k_wprep<<<4096, 256>>>(Whh);
    dim3 xg(256, 8);
    k_xproj<<<xg, 256>>>(X, Wih, bih, bhh);
    k_recur<<<R_CTAS, R_THREADS, SM_BYTES>>>();
    k_out<<<256, 256>>>(Who, bho, out);
}

// round 4
// speedup vs baseline: 1.5243x; 1.1090x over previous
#include <cuda_runtime.h>
#include <cuda_bf16.h>
#include <cstdint>

#define BATCH  64
#define SEQ    512
#define INDIM  512
#define HID    1024
#define OUTDIM 512

// ---------------- device scratch ---------------------------------------------
__device__ float          g_xp[(size_t)BATCH * SEQ * HID];     // 128 MB x-projection
__device__ __nv_bfloat16  g_xhi[(size_t)BATCH * SEQ * INDIM];  // X split hi
__device__ __nv_bfloat16  g_xlo[(size_t)BATCH * SEQ * INDIM];  // X split lo
__device__ __nv_bfloat16  g_wihhi[(size_t)HID * INDIM];        // W_ih hi
__device__ __nv_bfloat16  g_wihlo[(size_t)HID * INDIM];        // W_ih lo
__device__ float          g_bias[HID];                         // b_ih + b_hh
__device__ __nv_bfloat16  g_hhi[2 * BATCH * HID];              // hidden hi (ping-pong)
__device__ __nv_bfloat16  g_hlo[2 * BATCH * HID];              // hidden lo
__device__ __nv_bfloat16  g_whi[(size_t)HID * HID];            // W_hh hi
__device__ __nv_bfloat16  g_wlo[(size_t)HID * HID];            // W_hh lo
__device__ unsigned       g_sig[8][32];                        // [bg*2+half] padded counters

// ---------------- mma / ldmatrix helpers -------------------------------------
__device__ __forceinline__ void ldsm4(uint32_t &r0, uint32_t &r1, uint32_t &r2,
                                      uint32_t &r3, uint32_t addr) {
    asm volatile("ldmatrix.sync.aligned.m8n8.x4.shared.b16 {%0,%1,%2,%3}, [%4];"
                 : "=r"(r0), "=r"(r1), "=r"(r2), "=r"(r3) : "r"(addr));
}
__device__ __forceinline__ void mma16816(float* d, uint32_t a0, uint32_t a1,
                                         uint32_t a2, uint32_t a3,
                                         uint32_t b0, uint32_t b1) {
    asm volatile(
        "mma.sync.aligned.m16n8k16.row.col.f32.bf16.bf16.f32 "
        "{%0,%1,%2,%3},{%4,%5,%6,%7},{%8,%9},{%0,%1,%2,%3};"
        : "+f"(d[0]), "+f"(d[1]), "+f"(d[2]), "+f"(d[3])
        : "r"(a0), "r"(a1), "r"(a2), "r"(a3), "r"(b0), "r"(b1));
}
__device__ __forceinline__ void split_bf16(float v, __nv_bfloat16 &hi, __nv_bfloat16 &lo) {
    hi = __float2bfloat16(v);
    lo = __float2bfloat16(v - __bfloat162float(hi));
}

// ---------------- init: zero hidden buffers + signals ------------------------
__global__ void k_init() {
    int i = blockIdx.x * blockDim.x + threadIdx.x;    // 131072 threads
    if (i < 256) ((unsigned*)g_sig)[i] = 0u;
    if (i < 65536)       ((uint32_t*)g_hhi)[i] = 0u;
    else                 ((uint32_t*)g_hlo)[i - 65536] = 0u;
}

// ---------------- prep: split X, W_hh, W_ih; fold biases ---------------------
__global__ void k_prep(const float* __restrict__ X, const float* __restrict__ Whh,
                       const float* __restrict__ Wih, const float* __restrict__ bih,
                       const float* __restrict__ bhh) {
    int i = blockIdx.x * blockDim.x + threadIdx.x;    // 16777216 threads
    {   // X split (exactly BATCH*SEQ*INDIM threads)
        __nv_bfloat16 hi, lo;
        split_bf16(X[i], hi, lo);
        g_xhi[i] = hi; g_xlo[i] = lo;
    }
    if (i < HID * HID) {
        __nv_bfloat16 hi, lo;
        split_bf16(Whh[i], hi, lo);
        g_whi[i] = hi; g_wlo[i] = lo;
    }
    if (i < HID * INDIM) {
        __nv_bfloat16 hi, lo;
        split_bf16(Wih[i], hi, lo);
        g_wihhi[i] = hi; g_wihlo[i] = lo;
    }
    if (i < HID) g_bias[i] = bih[i] + bhh[i];
}

// ---------------- x_proj tensor-core GEMM ------------------------------------
// C[32768,1024] = Xsplit @ Wihsplit^T + bias.  BM=128, BN=64, BK=64.
// 8 warps (4m x 2n), warp tile 32m x 32n, 2-stage cp.async pipeline.
#define XROW     144                 // smem row stride bytes (64 bf16 + pad)
#define XA_COMP  (128 * XROW)        // 18432
#define XA_STAGE (2 * XA_COMP)       // 36864
#define XB_COMP  (64 * XROW)         // 9216
#define XB_STAGE (2 * XB_COMP)       // 18432
#define XS_A     0
#define XS_B     (2 * XA_STAGE)      // 73728
#define XS_BYTES (XS_B + 2 * XB_STAGE)  // 110592

__device__ __forceinline__ void xp_stage(uint32_t smb, int s, int kt,
                                         int m0, int n0, int tid) {
    const int kb = kt * 64;
#pragma unroll
    for (int r = 0; r < 8; r++) {                    // A: 2048 granules
        int q = tid + 256 * r;
        int c = q >> 10, row = (q >> 3) & 127, kg = q & 7;
        const __nv_bfloat16* src =
            (c ? g_xlo : g_xhi) + (size_t)(m0 + row) * INDIM + kb + kg * 8;
        uint32_t dst = smb + XS_A + s * XA_STAGE + c * XA_COMP + row * XROW + kg * 16;
        asm volatile("cp.async.cg.shared.global [%0], [%1], 16;" :: "r"(dst), "l"(src));
    }
#pragma unroll
    for (int r = 0; r < 4; r++) {                    // B: 1024 granules
        int q = tid + 256 * r;
        int c = q >> 9, row = (q >> 3) & 63, kg = q & 7;
        const __nv_bfloat16* src =
            (c ? g_wihlo : g_wihhi) + (size_t)(n0 + row) * INDIM + kb + kg * 8;
        uint32_t dst = smb + XS_B + s * XB_STAGE + c * XB_COMP + row * XROW + kg * 16;
        asm volatile("cp.async.cg.shared.global [%0], [%1], 16;" :: "r"(dst), "l"(src));
    }
}

__global__ __launch_bounds__(256) void k_xproj()
{
    extern __shared__ char smc[];
    const uint32_t smb = (uint32_t)__cvta_generic_to_shared(smc);

    const int tid  = threadIdx.x;
    const int lane = tid & 31;
    const int w    = tid >> 5;
    const int wm   = (w >> 1) * 32;
    const int wn   = (w & 1) * 32;
    const int m0   = blockIdx.x * 128;
    const int n0   = blockIdx.y * 64;

    float D1[2][4][4], D2[2][4][4];
#pragma unroll
    for (int i = 0; i < 2; i++)
#pragma unroll
        for (int j = 0; j < 4; j++)
#pragma unroll
            for (int r = 0; r < 4; r++) { D1[i][j][r] = 0.f; D2[i][j][r] = 0.f; }

    const uint32_t aoff = (wm + (lane & 15)) * XROW + (lane >> 4) * 16;
    const uint32_t boff = (wn + (lane & 7) + ((lane >> 4) << 3)) * XROW
                        + ((lane >> 3) & 1) * 16;

    xp_stage(smb, 0, 0, m0, n0, tid);
    asm volatile("cp.async.commit_group;");

    for (int kt = 0; kt < INDIM / 64; kt++) {
        const int s = kt & 1;
        if (kt + 1 < INDIM / 64) {
            xp_stage(smb, s ^ 1, kt + 1, m0, n0, tid);
            asm volatile("cp.async.commit_group;");
            asm volatile("cp.async.wait_group 1;");
        } else {
            asm volatile("cp.async.wait_group 0;");
        }
        __syncthreads();

        const uint32_t ah_b = smb + XS_A + s * XA_STAGE + aoff;
        const uint32_t al_b = ah_b + XA_COMP;
        const uint32_t bh_b = smb + XS_B + s * XB_STAGE + boff;
        const uint32_t bl_b = bh_b + XB_COMP;

#pragma unroll
        for (int ks = 0; ks < 4; ks++) {
            const uint32_t ka = ks * 32;
            uint32_t ah[2][4], al[2][4], bh[2][4], bl[2][4];
            ldsm4(ah[0][0], ah[0][1], ah[0][2], ah[0][3], ah_b + ka);
            ldsm4(ah[1][0], ah[1][1], ah[1][2], ah[1][3], ah_b + 16 * XROW + ka);
            ldsm4(al[0][0], al[0][1], al[0][2], al[0][3], al_b + ka);
            ldsm4(al[1][0], al[1][1], al[1][2], al[1][3], al_b + 16 * XROW + ka);
            ldsm4(bh[0][0], bh[0][1], bh[0][2], bh[0][3], bh_b + ka);
            ldsm4(bh[1][0], bh[1][1], bh[1][2], bh[1][3], bh_b + 16 * XROW + ka);
            ldsm4(bl[0][0], bl[0][1], bl[0][2], bl[0][3], bl_b + ka);
            ldsm4(bl[1][0], bl[1][1], bl[1][2], bl[1][3], bl_b + 16 * XROW + ka);
#pragma unroll
            for (int mi = 0; mi < 2; mi++)
#pragma unroll
                for (int tt = 0; tt < 4; tt++) {
                    int h2 = tt >> 1, p = (tt & 1) * 2;
                    mma16816(D1[mi][tt], ah[mi][0], ah[mi][1], ah[mi][2], ah[mi][3],
                             bh[h2][p], bh[h2][p + 1]);
                    mma16816(D2[mi][tt], al[mi][0], al[mi][1], al[mi][2], al[mi][3],
                             bh[h2][p], bh[h2][p + 1]);
                    mma16816(D2[mi][tt], ah[mi][0], ah[mi][1], ah[mi][2], ah[mi][3],
                             bl[h2][p], bl[h2][p + 1]);
                }
        }
        __syncthreads();
    }

    // epilogue
    const int rbase = lane >> 2;
    const int cbase = 2 * (lane & 3);
#pragma unroll
    for (int mi = 0; mi < 2; mi++)
#pragma unroll
        for (int tt = 0; tt < 4; tt++) {
            int gm = m0 + wm + mi * 16 + rbase;
            int gn = n0 + wn + tt * 8 + cbase;
            float2 b2 = *(const float2*)&g_bias[gn];
            float2 v;
            v.x = D1[mi][tt][0] + D2[mi][tt][0] + b2.x;
            v.y = D1[mi][tt][1] + D2[mi][tt][1] + b2.y;
            *(float2*)(g_xp + (size_t)gm * HID + gn) = v;
            v.x = D1[mi][tt][2] + D2[mi][tt][2] + b2.x;
            v.y = D1[mi][tt][3] + D2[mi][tt][3] + b2.y;
            *(float2*)(g_xp + (size_t)(gm + 8) * HID + gn) = v;
        }
}

// ---------------- recurrence: persistent tensor-core kernel ------------------
// 128 CTAs x 256 threads; CTA tile 16b x 32j; 4 independent bg chains of 32
// CTAs with split (j<512 / j>=512) producer-count signaling.
#define R_CTAS    128
#define R_THREADS 256

#define SM_WHI   0                       // [32][1032] bf16 (row 2064 B)
#define SM_WLO   66048
#define SM_HBUF  132096                  // 2 chunks x 2 comps x [16][520] bf16
#define HB_CHUNK 33280
#define HB_COMP  16640
#define HB_ROW   1040
#define SM_RED   198656                  // [8][528] f32
#define RED_ROW  528
#define SM_BYTES 215552

__device__ __forceinline__ void stage_chunk(uint32_t dst_base,
                                            const __nv_bfloat16* ghi,
                                            const __nv_bfloat16* glo, int tid) {
#pragma unroll
    for (int r = 0; r < 8; r++) {
        int q    = tid + R_THREADS * r;
        int comp = q >> 10, rr = (q >> 6) & 15, g = q & 63;
        const __nv_bfloat16* src = (comp ? glo : ghi) + rr * HID + g * 8;
        uint32_t dst = dst_base + comp * HB_COMP + rr * HB_ROW + g * 16;
        asm volatile("cp.async.cg.shared.global [%0], [%1], 16;"
                     :: "r"(dst), "l"(src));
    }
}

__global__ __launch_bounds__(R_THREADS, 1) void k_recur()
{
    extern __shared__ char smc[];
    const uint32_t smb = (uint32_t)__cvta_generic_to_shared(smc);
    float* redf = (float*)(smc + SM_RED);

    const int tid  = threadIdx.x;
    const int lane = tid & 31;
    const int w    = tid >> 5;
    const int jg   = blockIdx.x & 31;
    const int bgi  = blockIdx.x >> 5;
    const int cta_j0 = jg * 32;
    const int cta_b0 = bgi * 16;

    unsigned* my_sig = &g_sig[bgi * 2 + (jg >> 4)][0];
    volatile unsigned* sigA = &g_sig[bgi * 2][0];
    volatile unsigned* sigB = &g_sig[bgi * 2 + 1][0];

    // ---- load W slice (32 j x 1024 k, hi+lo) into padded smem ----
#pragma unroll 8
    for (int it = 0; it < 32; it++) {
        int q = tid + R_THREADS * it;
        int comp = q >> 12, row = (q >> 7) & 31, g = q & 127;
        const __nv_bfloat16* src =
            (comp ? g_wlo : g_whi) + (size_t)(cta_j0 + row) * HID + g * 8;
        *(uint4*)(smc + (comp ? SM_WLO : SM_WHI) + row * 2064 + g * 16) =
            *(const uint4*)src;
    }
    __syncthreads();

    uint32_t a_base[2];
#pragma unroll
    for (int comp = 0; comp < 2; comp++)
        a_base[comp] = smb + SM_HBUF + comp * HB_COMP
                     + (lane & 15) * HB_ROW + (lane >> 4) * 16;
    uint32_t b_base[2][2];
#pragma unroll
    for (int comp = 0; comp < 2; comp++)
#pragma unroll
        for (int half = 0; half < 2; half++)
            b_base[comp][half] = smb + (comp ? SM_WLO : SM_WHI)
                + (half * 16 + (lane >> 4) * 8 + (lane & 7)) * 2064
                + ((lane >> 3) & 1) * 16;

    const int koffw = w * 128;

    const int o0 = tid * 2;
    const int bl = o0 >> 5, jl = o0 & 31;

    for (int t = 0; t < SEQ; t++) {
        const __nv_bfloat16* hch = g_hhi + (t & 1) * (BATCH * HID) + cta_b0 * HID;
        const __nv_bfloat16* hcl = g_hlo + (t & 1) * (BATCH * HID) + cta_b0 * HID;
        __nv_bfloat16* hnh = g_hhi + ((t + 1) & 1) * (BATCH * HID);
        __nv_bfloat16* hnl = g_hlo + ((t + 1) & 1) * (BATCH * HID);

        float2 xp = __ldg((const float2*)
            (g_xp + ((size_t)(cta_b0 + bl) * SEQ + t) * HID + cta_j0 + jl));

        float D1[4][4], D2[4][4];
#pragma unroll
        for (int i = 0; i < 4; i++)
#pragma unroll
            for (int j = 0; j < 4; j++) { D1[i][j] = 0.f; D2[i][j] = 0.f; }

        const unsigned need = 16u * (unsigned)t;
        if (t) {
            if (tid == 0) while (*sigA < need) { }
            __syncthreads();
        }
        stage_chunk(smb + SM_HBUF, hch, hcl, tid);
        asm volatile("cp.async.commit_group;");
        if (t) {
            if (tid == 0) while (*sigB < need) { }
            __syncthreads();
        }
        stage_chunk(smb + SM_HBUF + HB_CHUNK, hch + 512, hcl + 512, tid);
        asm volatile("cp.async.commit_group;");

        asm volatile("cp.async.wait_group 1;");
        __syncthreads();

#pragma unroll
        for (int c = 0; c < 2; c++) {
            if (c == 1) {
                asm volatile("cp.async.wait_group 0;");
                __syncthreads();
            }
            const uint32_t cb = c * HB_CHUNK;
            const uint32_t cw = c * 1024;
#pragma unroll
            for (int ks = 0; ks < 4; ks++) {
                const uint32_t ka = koffw + ks * 32;
                uint32_t ah[4], al[4], bh[2][4], bl2[2][4];
                ldsm4(ah[0], ah[1], ah[2], ah[3], a_base[0] + cb + ka);
                ldsm4(al[0], al[1], al[2], al[3], a_base[1] + cb + ka);
                ldsm4(bh[0][0], bh[0][1], bh[0][2], bh[0][3], b_base[0][0] + cw + ka);
                ldsm4(bh[1][0], bh[1][1], bh[1][2], bh[1][3], b_base[0][1] + cw + ka);
                ldsm4(bl2[0][0], bl2[0][1], bl2[0][2], bl2[0][3], b_base[1][0] + cw + ka);
                ldsm4(bl2[1][0], bl2[1][1], bl2[1][2], bl2[1][3], b_base[1][1] + cw + ka);
#pragma unroll
                for (int tt = 0; tt < 4; tt++) {
                    int h2 = tt >> 1, p = (tt & 1) * 2;
                    mma16816(D1[tt], ah[0], ah[1], ah[2], ah[3],
                             bh[h2][p], bh[h2][p + 1]);
                }
#pragma unroll
                for (int tt = 0; tt < 4; tt++) {
                    int h2 = tt >> 1, p = (tt & 1) * 2;
                    mma16816(D2[tt], al[0], al[1], al[2], al[3],
                             bh[h2][p], bh[h2][p + 1]);
                }
#pragma unroll
                for (int tt = 0; tt < 4; tt++) {
                    int h2 = tt >> 1, p = (tt & 1) * 2;
                    mma16816(D2[tt], ah[0], ah[1], ah[2], ah[3],
                             bl2[h2][p], bl2[h2][p + 1]);
                }
            }
        }
        __syncthreads();   // all warps done with hbuf + prior redf reads

        // ---- cross-warp k reduction via smem ----
#pragma unroll
        for (int tt = 0; tt < 4; tt++)
#pragma unroll
            for (int r = 0; r < 4; r++) {
                int b = (lane >> 2) + ((r >= 2) ? 8 : 0);
                int j = tt * 8 + 2 * (lane & 3) + (r & 1);
                redf[w * RED_ROW + b * 33 + j] = D1[tt][r] + D2[tt][r];
            }
        __syncthreads();

        float v0 = 0.f, v1 = 0.f;
#pragma unroll
        for (int ww = 0; ww < 8; ww++) {
            v0 += redf[ww * RED_ROW + bl * 33 + jl];
            v1 += redf[ww * RED_ROW + bl * 33 + jl + 1];
        }
        v0 = tanhf(v0 + xp.x);
        v1 = tanhf(v1 + xp.y);

        __nv_bfloat16 h0, l0, h1, l1;
        split_bf16(v0, h0, l0);
        split_bf16(v1, h1, l1);
        size_t oidx = (size_t)(cta_b0 + bl) * HID + cta_j0 + jl;
        __nv_bfloat162 ph; ph.x = h0; ph.y = h1;
        __nv_bfloat162 pl; pl.x = l0; pl.y = l1;
        *(__nv_bfloat162*)(hnh + oidx) = ph;
        *(__nv_bfloat162*)(hnl + oidx) = pl;

        __threadfence();
        __syncthreads();
        if (tid == 0) atomicAdd(my_sig, 1u);
    }
}

// ---------------- output projection ------------------------------------------
__global__ __launch_bounds__(256) void k_out(
    const float* __restrict__ Who, const float* __restrict__ bho,
    float* __restrict__ out)
{
    const int lane = threadIdx.x & 31;
    const int gw   = blockIdx.x * 8 + (threadIdx.x >> 5);
    const int o0   = (gw >> 3) * 2;
    const int b0   = (gw & 7) * 8;

    const float4* W0 = (const float4*)(Who + (size_t)o0 * HID);
    const float4* W1 = (const float4*)(Who + (size_t)(o0 + 1) * HID);
    float4 wr0[8], wr1[8];
#pragma unroll
    for (int i = 0; i < 8; i++) {
        wr0[i] = W0[i * 32 + lane];
        wr1[i] = W1[i * 32 + lane];
    }
    float bias0 = __ldg(&bho[o0]), bias1 = __ldg(&bho[o0 + 1]);

#pragma unroll
    for (int b = 0; b < 8; b++) {
        const __nv_bfloat16* hh = g_hhi + (size_t)(b0 + b) * HID;  // final h in buf 0
        const __nv_bfloat16* hl = g_hlo + (size_t)(b0 + b) * HID;
        float a0 = 0.f, a1 = 0.f;
#pragma unroll
        for (int i = 0; i < 8; i++) {
            int k0 = lane * 4 + i * 128;
            __nv_bfloat162 ph0 = *(const __nv_bfloat162*)(hh + k0);
            __nv_bfloat162 ph1 = *(const __nv_bfloat162*)(hh + k0 + 2);
            __nv_bfloat162 pl0 = *(const __nv_bfloat162*)(hl + k0);
            __nv_bfloat162 pl1 = *(const __nv_bfloat162*)(hl + k0 + 2);
            float2 f0 = __bfloat1622float2(ph0), g0 = __bfloat1622float2(pl0);
            float2 f1 = __bfloat1622float2(ph1), g1 = __bfloat1622float2(pl1);
            float hx = f0.x + g0.x, hy = f0.y + g0.y;
            float hz = f1.x + g1.x, hw = f1.y + g1.y;
            a0 += hx * wr0[i].x + hy * wr0[i].y + hz * wr0[i].z + hw * wr0[i].w;
            a1 += hx * wr1[i].x + hy * wr1[i].y + hz * wr1[i].z + hw * wr1[i].w;
        }
#pragma unroll
        for (int off = 16; off; off >>= 1) {
            a0 += __shfl_xor_sync(0xffffffffu, a0, off);
            a1 += __shfl_xor_sync(0xffffffffu, a1, off);
        }
        if (lane == 0) {
            out[(size_t)(b0 + b) * OUTDIM + o0]     = a0 + bias0;
            out[(size_t)(b0 + b) * OUTDIM + o0 + 1] = a1 + bias1;
        }
    }
}

// ---------------- launch ------------------------------------------------------
extern "C" void kernel_launch(void* const* d_in, const int* in_sizes, int n_in,
                              void* d_out, int out_size)
{
    (void)in_sizes; (void)n_in; (void)out_size;
    const float* X   = (const float*)d_in[0];
    const float* Wih = (const float*)d_in[1];
    const float* bih = (const float*)d_in[2];
    const float* Whh = (const float*)d_in[3];
    const float* bhh = (const float*)d_in[4];
    const float* Who = (const float*)d_in[5];
    const float* bho = (const float*)d_in[6];
    float* out = (float*)d_out;

    cudaFuncSetAttribute(k_xproj, cudaFuncAttributeMaxDynamicSharedMemorySize,
                         XS_BYTES);
    cudaFuncSetAttribute(k_recur, cudaFuncAttributeMaxDynamicSharedMemorySize,
                         SM_BYTES);

    k_init<<<512, 256>>>();
    k_prep<<<65536, 256>>>(X, Whh, Wih, bih, bhh);
    dim3 xg(BATCH * SEQ / 128, HID / 64);
    k_xproj<<<xg, 256, XS_BYTES>>>();
    k_recur<<<R_CTAS, R_THREADS, SM_BYTES>>>();
    k_out<<<256, 256>>>(Who, bho, out);
}

// round 5
// speedup vs baseline: 1.7668x; 1.1591x over previous
#include <cuda_runtime.h>
#include <cuda_bf16.h>
#include <cstdint>

#define BATCH  64
#define SEQ    512
#define INDIM  512
#define HID    1024
#define OUTDIM 512

// ---------------- device scratch ---------------------------------------------
__device__ float          g_xp[(size_t)BATCH * SEQ * HID];     // 128 MB x-projection
__device__ __nv_bfloat16  g_xhi[(size_t)BATCH * SEQ * INDIM];  // X split hi
__device__ __nv_bfloat16  g_xlo[(size_t)BATCH * SEQ * INDIM];  // X split lo
__device__ __nv_bfloat16  g_wihhi[(size_t)HID * INDIM];        // W_ih hi
__device__ __nv_bfloat16  g_wihlo[(size_t)HID * INDIM];        // W_ih lo
__device__ float          g_bias[HID];                         // b_ih + b_hh
__device__ __nv_bfloat16  g_hhi[2 * BATCH * HID];              // hidden hi (ping-pong)
__device__ __nv_bfloat16  g_hlo[2 * BATCH * HID];              // hidden lo
__device__ __nv_bfloat16  g_whi[(size_t)HID * HID];            // W_hh hi
__device__ __nv_bfloat16  g_wlo[(size_t)HID * HID];            // W_hh lo
__device__ unsigned       g_sig[4][32];                        // per-bg counters (padded)

// ---------------- mma / ldmatrix helpers -------------------------------------
__device__ __forceinline__ void ldsm4(uint32_t &r0, uint32_t &r1, uint32_t &r2,
                                      uint32_t &r3, uint32_t addr) {
    asm volatile("ldmatrix.sync.aligned.m8n8.x4.shared.b16 {%0,%1,%2,%3}, [%4];"
                 : "=r"(r0), "=r"(r1), "=r"(r2), "=r"(r3) : "r"(addr));
}
__device__ __forceinline__ void mma16816(float* d, uint32_t a0, uint32_t a1,
                                         uint32_t a2, uint32_t a3,
                                         uint32_t b0, uint32_t b1) {
    asm volatile(
        "mma.sync.aligned.m16n8k16.row.col.f32.bf16.bf16.f32 "
        "{%0,%1,%2,%3},{%4,%5,%6,%7},{%8,%9},{%0,%1,%2,%3};"
        : "+f"(d[0]), "+f"(d[1]), "+f"(d[2]), "+f"(d[3])
        : "r"(a0), "r"(a1), "r"(a2), "r"(a3), "r"(b0), "r"(b1));
}
__device__ __forceinline__ void split_bf16(float v, __nv_bfloat16 &hi, __nv_bfloat16 &lo) {
    hi = __float2bfloat16(v);
    lo = __float2bfloat16(v - __bfloat162float(hi));
}

// ---------------- init: zero hidden buffers + signals ------------------------
__global__ void k_init() {
    int i = blockIdx.x * blockDim.x + threadIdx.x;    // 131072 threads
    if (i < 128) ((unsigned*)g_sig)[i] = 0u;
    if (i < 65536)       ((uint32_t*)g_hhi)[i] = 0u;
    else                 ((uint32_t*)g_hlo)[i - 65536] = 0u;
}

// ---------------- prep: split X, W_hh, W_ih; fold biases ---------------------
__global__ void k_prep(const float* __restrict__ X, const float* __restrict__ Whh,
                       const float* __restrict__ Wih, const float* __restrict__ bih,
                       const float* __restrict__ bhh) {
    int i = blockIdx.x * blockDim.x + threadIdx.x;    // 16777216 threads
    {
        __nv_bfloat16 hi, lo;
        split_bf16(X[i], hi, lo);
        g_xhi[i] = hi; g_xlo[i] = lo;
    }
    if (i < HID * HID) {
        __nv_bfloat16 hi, lo;
        split_bf16(Whh[i], hi, lo);
        g_whi[i] = hi; g_wlo[i] = lo;
    }
    if (i < HID * INDIM) {
        __nv_bfloat16 hi, lo;
        split_bf16(Wih[i], hi, lo);
        g_wihhi[i] = hi; g_wihlo[i] = lo;
    }
    if (i < HID) g_bias[i] = bih[i] + bhh[i];
}

// ---------------- x_proj tensor-core GEMM ------------------------------------
#define XROW     144
#define XA_COMP  (128 * XROW)
#define XA_STAGE (2 * XA_COMP)
#define XB_COMP  (64 * XROW)
#define XB_STAGE (2 * XB_COMP)
#define XS_A     0
#define XS_B     (2 * XA_STAGE)
#define XS_BYTES (XS_B + 2 * XB_STAGE)

__device__ __forceinline__ void xp_stage(uint32_t smb, int s, int kt,
                                         int m0, int n0, int tid) {
    const int kb = kt * 64;
#pragma unroll
    for (int r = 0; r < 8; r++) {
        int q = tid + 256 * r;
        int c = q >> 10, row = (q >> 3) & 127, kg = q & 7;
        const __nv_bfloat16* src =
            (c ? g_xlo : g_xhi) + (size_t)(m0 + row) * INDIM + kb + kg * 8;
        uint32_t dst = smb + XS_A + s * XA_STAGE + c * XA_COMP + row * XROW + kg * 16;
        asm volatile("cp.async.cg.shared.global [%0], [%1], 16;" :: "r"(dst), "l"(src));
    }
#pragma unroll
    for (int r = 0; r < 4; r++) {
        int q = tid + 256 * r;
        int c = q >> 9, row = (q >> 3) & 63, kg = q & 7;
        const __nv_bfloat16* src =
            (c ? g_wihlo : g_wihhi) + (size_t)(n0 + row) * INDIM + kb + kg * 8;
        uint32_t dst = smb + XS_B + s * XB_STAGE + c * XB_COMP + row * XROW + kg * 16;
        asm volatile("cp.async.cg.shared.global [%0], [%1], 16;" :: "r"(dst), "l"(src));
    }
}

__global__ __launch_bounds__(256) void k_xproj()
{
    extern __shared__ char smc[];
    const uint32_t smb = (uint32_t)__cvta_generic_to_shared(smc);

    const int tid  = threadIdx.x;
    const int lane = tid & 31;
    const int w    = tid >> 5;
    const int wm   = (w >> 1) * 32;
    const int wn   = (w & 1) * 32;
    const int m0   = blockIdx.x * 128;
    const int n0   = blockIdx.y * 64;

    float D1[2][4][4], D2[2][4][4];
#pragma unroll
    for (int i = 0; i < 2; i++)
#pragma unroll
        for (int j = 0; j < 4; j++)
#pragma unroll
            for (int r = 0; r < 4; r++) { D1[i][j][r] = 0.f; D2[i][j][r] = 0.f; }

    const uint32_t aoff = (wm + (lane & 15)) * XROW + (lane >> 4) * 16;
    const uint32_t boff = (wn + (lane & 7) + ((lane >> 4) << 3)) * XROW
                        + ((lane >> 3) & 1) * 16;

    xp_stage(smb, 0, 0, m0, n0, tid);
    asm volatile("cp.async.commit_group;");

    for (int kt = 0; kt < INDIM / 64; kt++) {
        const int s = kt & 1;
        if (kt + 1 < INDIM / 64) {
            xp_stage(smb, s ^ 1, kt + 1, m0, n0, tid);
            asm volatile("cp.async.commit_group;");
            asm volatile("cp.async.wait_group 1;");
        } else {
            asm volatile("cp.async.wait_group 0;");
        }
        __syncthreads();

        const uint32_t ah_b = smb + XS_A + s * XA_STAGE + aoff;
        const uint32_t al_b = ah_b + XA_COMP;
        const uint32_t bh_b = smb + XS_B + s * XB_STAGE + boff;
        const uint32_t bl_b = bh_b + XB_COMP;

#pragma unroll
        for (int ks = 0; ks < 4; ks++) {
            const uint32_t ka = ks * 32;
            uint32_t ah[2][4], al[2][4], bh[2][4], bl[2][4];
            ldsm4(ah[0][0], ah[0][1], ah[0][2], ah[0][3], ah_b + ka);
            ldsm4(ah[1][0], ah[1][1], ah[1][2], ah[1][3], ah_b + 16 * XROW + ka);
            ldsm4(al[0][0], al[0][1], al[0][2], al[0][3], al_b + ka);
            ldsm4(al[1][0], al[1][1], al[1][2], al[1][3], al_b + 16 * XROW + ka);
            ldsm4(bh[0][0], bh[0][1], bh[0][2], bh[0][3], bh_b + ka);
            ldsm4(bh[1][0], bh[1][1], bh[1][2], bh[1][3], bh_b + 16 * XROW + ka);
            ldsm4(bl[0][0], bl[0][1], bl[0][2], bl[0][3], bl_b + ka);
            ldsm4(bl[1][0], bl[1][1], bl[1][2], bl[1][3], bl_b + 16 * XROW + ka);
#pragma unroll
            for (int mi = 0; mi < 2; mi++)
#pragma unroll
                for (int tt = 0; tt < 4; tt++) {
                    int h2 = tt >> 1, p = (tt & 1) * 2;
                    mma16816(D1[mi][tt], ah[mi][0], ah[mi][1], ah[mi][2], ah[mi][3],
                             bh[h2][p], bh[h2][p + 1]);
                    mma16816(D2[mi][tt], al[mi][0], al[mi][1], al[mi][2], al[mi][3],
                             bh[h2][p], bh[h2][p + 1]);
                    mma16816(D2[mi][tt], ah[mi][0], ah[mi][1], ah[mi][2], ah[mi][3],
                             bl[h2][p], bl[h2][p + 1]);
                }
        }
        __syncthreads();
    }

    const int rbase = lane >> 2;
    const int cbase = 2 * (lane & 3);
#pragma unroll
    for (int mi = 0; mi < 2; mi++)
#pragma unroll
        for (int tt = 0; tt < 4; tt++) {
            int gm = m0 + wm + mi * 16 + rbase;
            int gn = n0 + wn + tt * 8 + cbase;
            float2 b2 = *(const float2*)&g_bias[gn];
            float2 v;
            v.x = D1[mi][tt][0] + D2[mi][tt][0] + b2.x;
            v.y = D1[mi][tt][1] + D2[mi][tt][1] + b2.y;
            *(float2*)(g_xp + (size_t)gm * HID + gn) = v;
            v.x = D1[mi][tt][2] + D2[mi][tt][2] + b2.x;
            v.y = D1[mi][tt][3] + D2[mi][tt][3] + b2.y;
            *(float2*)(g_xp + (size_t)(gm + 8) * HID + gn) = v;
        }
}

// ---------------- recurrence: persistent tensor-core kernel ------------------
// 128 CTAs x 256 threads; CTA tile 16b x 32j; 4 independent 32-CTA bg chains,
// single release/acquire counter per chain. W_hh fragments hoisted to regs.
#define R_CTAS    128
#define R_THREADS 256

#define SM_WHI   0                       // [32][1032] bf16 (row 2064 B)
#define SM_WLO   66048
#define SM_HBUF  132096                  // 2 chunks x 2 comps x [16][520] bf16
#define HB_CHUNK 33280
#define HB_COMP  16640
#define HB_ROW   1040
#define SM_RED   198656                  // [8][528] f32
#define RED_ROW  528
#define SM_BYTES 215552

__device__ __forceinline__ void stage_chunk(uint32_t dst_base,
                                            const __nv_bfloat16* ghi,
                                            const __nv_bfloat16* glo, int tid) {
#pragma unroll
    for (int r = 0; r < 8; r++) {
        int q    = tid + R_THREADS * r;
        int comp = q >> 10, rr = (q >> 6) & 15, g = q & 63;
        const __nv_bfloat16* src = (comp ? glo : ghi) + rr * HID + g * 8;
        uint32_t dst = dst_base + comp * HB_COMP + rr * HB_ROW + g * 16;
        asm volatile("cp.async.cg.shared.global [%0], [%1], 16;"
                     :: "r"(dst), "l"(src));
    }
}

__global__ __launch_bounds__(R_THREADS, 1) void k_recur()
{
    extern __shared__ char smc[];
    const uint32_t smb = (uint32_t)__cvta_generic_to_shared(smc);
    float* redf = (float*)(smc + SM_RED);

    const int tid  = threadIdx.x;
    const int lane = tid & 31;
    const int w    = tid >> 5;
    const int jg   = blockIdx.x & 31;
    const int bgi  = blockIdx.x >> 5;
    const int cta_j0 = jg * 32;
    const int cta_b0 = bgi * 16;

    unsigned* my_sig = &g_sig[bgi][0];

    // ---- load W slice (32 j x 1024 k, hi+lo) into padded smem ----
#pragma unroll 8
    for (int it = 0; it < 32; it++) {
        int q = tid + R_THREADS * it;
        int comp = q >> 12, row = (q >> 7) & 31, g = q & 127;
        const __nv_bfloat16* src =
            (comp ? g_wlo : g_whi) + (size_t)(cta_j0 + row) * HID + g * 8;
        *(uint4*)(smc + (comp ? SM_WLO : SM_WHI) + row * 2064 + g * 16) =
            *(const uint4*)src;
    }
    __syncthreads();

    uint32_t a_base[2];
#pragma unroll
    for (int comp = 0; comp < 2; comp++)
        a_base[comp] = smb + SM_HBUF + comp * HB_COMP
                     + (lane & 15) * HB_ROW + (lane >> 4) * 16;
    uint32_t b_base[2][2];
#pragma unroll
    for (int comp = 0; comp < 2; comp++)
#pragma unroll
        for (int half = 0; half < 2; half++)
            b_base[comp][half] = smb + (comp ? SM_WLO : SM_WHI)
                + (half * 16 + (lane >> 4) * 8 + (lane & 7)) * 2064
                + ((lane >> 3) & 1) * 16;

    const int koffw = w * 128;

    // ---- hoist all W fragments into registers (resident for 512 steps) ----
    uint32_t wf[2][4][2][2][4];    // [chunk][ks][comp][half][reg]
#pragma unroll
    for (int c = 0; c < 2; c++)
#pragma unroll
        for (int ks = 0; ks < 4; ks++)
#pragma unroll
            for (int comp = 0; comp < 2; comp++)
#pragma unroll
                for (int half = 0; half < 2; half++)
                    ldsm4(wf[c][ks][comp][half][0], wf[c][ks][comp][half][1],
                          wf[c][ks][comp][half][2], wf[c][ks][comp][half][3],
                          b_base[comp][half] + c * 1024 + koffw + ks * 32);

    const int o0 = tid * 2;
    const int bl = o0 >> 5, jl = o0 & 31;

    for (int t = 0; t < SEQ; t++) {
        const __nv_bfloat16* hch = g_hhi + (t & 1) * (BATCH * HID) + cta_b0 * HID;
        const __nv_bfloat16* hcl = g_hlo + (t & 1) * (BATCH * HID) + cta_b0 * HID;
        __nv_bfloat16* hnh = g_hhi + ((t + 1) & 1) * (BATCH * HID);
        __nv_bfloat16* hnl = g_hlo + ((t + 1) & 1) * (BATCH * HID);

        // wait for all 32 peer CTAs of this bg chain to finish step t-1
        if (t) {
            const unsigned need = 32u * (unsigned)t;
            if (tid == 0) {
                unsigned v;
                do {
                    asm volatile("ld.acquire.gpu.global.u32 %0, [%1];"
                                 : "=r"(v) : "l"(my_sig));
                } while (v < need);
            }
            __syncthreads();
        }

        stage_chunk(smb + SM_HBUF, hch, hcl, tid);
        asm volatile("cp.async.commit_group;");
        stage_chunk(smb + SM_HBUF + HB_CHUNK, hch + 512, hcl + 512, tid);
        asm volatile("cp.async.commit_group;");

        float2 xp = __ldg((const float2*)
            (g_xp + ((size_t)(cta_b0 + bl) * SEQ + t) * HID + cta_j0 + jl));

        float D1[4][4], D2[4][4];
#pragma unroll
        for (int i = 0; i < 4; i++)
#pragma unroll
            for (int j = 0; j < 4; j++) { D1[i][j] = 0.f; D2[i][j] = 0.f; }

        asm volatile("cp.async.wait_group 1;");
        __syncthreads();

#pragma unroll
        for (int c = 0; c < 2; c++) {
            if (c == 1) {
                asm volatile("cp.async.wait_group 0;");
                __syncthreads();
            }
            const uint32_t cb = c * HB_CHUNK;
#pragma unroll
            for (int ks = 0; ks < 4; ks++) {
                const uint32_t ka = koffw + ks * 32;
                uint32_t ah[4], al[4];
                ldsm4(ah[0], ah[1], ah[2], ah[3], a_base[0] + cb + ka);
                ldsm4(al[0], al[1], al[2], al[3], a_base[1] + cb + ka);
#pragma unroll
                for (int tt = 0; tt < 4; tt++) {
                    int h2 = tt >> 1, p = (tt & 1) * 2;
                    mma16816(D1[tt], ah[0], ah[1], ah[2], ah[3],
                             wf[c][ks][0][h2][p], wf[c][ks][0][h2][p + 1]);
                }
#pragma unroll
                for (int tt = 0; tt < 4; tt++) {
                    int h2 = tt >> 1, p = (tt & 1) * 2;
                    mma16816(D2[tt], al[0], al[1], al[2], al[3],
                             wf[c][ks][0][h2][p], wf[c][ks][0][h2][p + 1]);
                }
#pragma unroll
                for (int tt = 0; tt < 4; tt++) {
                    int h2 = tt >> 1, p = (tt & 1) * 2;
                    mma16816(D2[tt], ah[0], ah[1], ah[2], ah[3],
                             wf[c][ks][1][h2][p], wf[c][ks][1][h2][p + 1]);
                }
            }
        }

        // ---- cross-warp k reduction via smem ----
#pragma unroll
        for (int tt = 0; tt < 4; tt++)
#pragma unroll
            for (int r = 0; r < 4; r++) {
                int b = (lane >> 2) + ((r >= 2) ? 8 : 0);
                int j = tt * 8 + 2 * (lane & 3) + (r & 1);
                redf[w * RED_ROW + b * 33 + j] = D1[tt][r] + D2[tt][r];
            }
        __syncthreads();

        float v0 = 0.f, v1 = 0.f;
#pragma unroll
        for (int ww = 0; ww < 8; ww++) {
            v0 += redf[ww * RED_ROW + bl * 33 + jl];
            v1 += redf[ww * RED_ROW + bl * 33 + jl + 1];
        }
        v0 = tanhf(v0 + xp.x);
        v1 = tanhf(v1 + xp.y);

        __nv_bfloat16 h0, l0, h1, l1;
        split_bf16(v0, h0, l0);
        split_bf16(v1, h1, l1);
        size_t oidx = (size_t)(cta_b0 + bl) * HID + cta_j0 + jl;
        __nv_bfloat162 ph; ph.x = h0; ph.y = h1;
        __nv_bfloat162 pl; pl.x = l0; pl.y = l1;
        *(__nv_bfloat162*)(hnh + oidx) = ph;
        *(__nv_bfloat162*)(hnl + oidx) = pl;

        __syncthreads();
        if (tid == 0)
            asm volatile("red.release.gpu.global.add.u32 [%0], %1;"
                         :: "l"(my_sig), "r"(1u));
    }
}

// ---------------- output projection ------------------------------------------
__global__ __launch_bounds__(256) void k_out(
    const float* __restrict__ Who, const float* __restrict__ bho,
    float* __restrict__ out)
{
    const int lane = threadIdx.x & 31;
    const int gw   = blockIdx.x * 8 + (threadIdx.x >> 5);
    const int o0   = (gw >> 3) * 2;
    const int b0   = (gw & 7) * 8;

    const float4* W0 = (const float4*)(Who + (size_t)o0 * HID);
    const float4* W1 = (const float4*)(Who + (size_t)(o0 + 1) * HID);
    float4 wr0[8], wr1[8];
#pragma unroll
    for (int i = 0; i < 8; i++) {
        wr0[i] = W0[i * 32 + lane];
        wr1[i] = W1[i * 32 + lane];
    }
    float bias0 = __ldg(&bho[o0]), bias1 = __ldg(&bho[o0 + 1]);

#pragma unroll
    for (int b = 0; b < 8; b++) {
        const __nv_bfloat16* hh = g_hhi + (size_t)(b0 + b) * HID;  // final h in buf 0
        const __nv_bfloat16* hl = g_hlo + (size_t)(b0 + b) * HID;
        float a0 = 0.f, a1 = 0.f;
#pragma unroll
        for (int i = 0; i < 8; i++) {
            int k0 = lane * 4 + i * 128;
            __nv_bfloat162 ph0 = *(const __nv_bfloat162*)(hh + k0);
            __nv_bfloat162 ph1 = *(const __nv_bfloat162*)(hh + k0 + 2);
            __nv_bfloat162 pl0 = *(const __nv_bfloat162*)(hl + k0);
            __nv_bfloat162 pl1 = *(const __nv_bfloat162*)(hl + k0 + 2);
            float2 f0 = __bfloat1622float2(ph0), g0 = __bfloat1622float2(pl0);
            float2 f1 = __bfloat1622float2(ph1), g1 = __bfloat1622float2(pl1);
            float hx = f0.x + g0.x, hy = f0.y + g0.y;
            float hz = f1.x + g1.x, hw = f1.y + g1.y;
            a0 += hx * wr0[i].x + hy * wr0[i].y + hz * wr0[i].z + hw * wr0[i].w;
            a1 += hx * wr1[i].x + hy * wr1[i].y + hz * wr1[i].z + hw * wr1[i].w;
        }
#pragma unroll
        for (int off = 16; off; off >>= 1) {
            a0 += __shfl_xor_sync(0xffffffffu, a0, off);
            a1 += __shfl_xor_sync(0xffffffffu, a1, off);
        }
        if (lane == 0) {
            out[(size_t)(b0 + b) * OUTDIM + o0]     = a0 + bias0;
            out[(size_t)(b0 + b) * OUTDIM + o0 + 1] = a1 + bias1;
        }
    }
}

// ---------------- launch ------------------------------------------------------
extern "C" void kernel_launch(void* const* d_in, const int* in_sizes, int n_in,
                              void* d_out, int out_size)
{
    (void)in_sizes; (void)n_in; (void)out_size;
    const float* X   = (const float*)d_in[0];
    const float* Wih = (const float*)d_in[1];
    const float* bih = (const float*)d_in[2];
    const float* Whh = (const float*)d_in[3];
    const float* bhh = (const float*)d_in[4];
    const float* Who = (const float*)d_in[5];
    const float* bho = (const float*)d_in[6];
    float* out = (float*)d_out;

    cudaFuncSetAttribute(k_xproj, cudaFuncAttributeMaxDynamicSharedMemorySize,
                         XS_BYTES);
    cudaFuncSetAttribute(k_recur, cudaFuncAttributeMaxDynamicSharedMemorySize,
                         SM_BYTES);

    k_init<<<512, 256>>>();
    k_prep<<<65536, 256>>>(X, Whh, Wih, bih, bhh);
    dim3 xg(BATCH * SEQ / 128, HID / 64);
    k_xproj<<<xg, 256, XS_BYTES>>>();
    k_recur<<<R_CTAS, R_THREADS, SM_BYTES>>>();
    k_out<<<256, 256>>>(Who, bho, out);
}